// round 14
// baseline (speedup 1.0000x reference)
#include <cuda_runtime.h>
#include <cstdint>

#define NN 100000          // nodes
#define NE 1600000         // edges
#define HID 64
#define NLAYERS 3
#define NB ((NN + 255) / 256)   // 391 node blocks

// ---------------- scratch (no allocations allowed) ----------------
__device__ float g_z[NN * HID];
__device__ float g_h[NN * HID];
__device__ float g_stats[2 * HID];   // [0:64) sum, [64:128) sumsq
__device__ float g_ss[2 * HID];      // [0:64) scale, [64:128) shift
__device__ int   g_deg[NN];
__device__ int   g_off[NN];
__device__ int   g_cur[NN];
__device__ int   g_elist[NE];
__device__ int   g_bsum[NB];
__device__ int   g_bpre[NB];
__device__ int   g_is64;

// ---------------- helpers ----------------
__device__ __forceinline__ float tf32_rna(float x) {
    uint32_t u;
    asm("cvt.rna.tf32.f32 %0, %1;" : "=r"(u) : "f"(x));
    return __uint_as_float(u);
}

#define MMA_TF32(d, a, b)                                                     \
    asm volatile("mma.sync.aligned.m16n8k8.row.col.f32.tf32.tf32.f32 "        \
                 "{%0,%1,%2,%3}, {%4,%5,%6,%7}, {%8,%9}, {%0,%1,%2,%3};"      \
                 : "+f"((d)[0]), "+f"((d)[1]), "+f"((d)[2]), "+f"((d)[3])     \
                 : "r"((a)[0]), "r"((a)[1]), "r"((a)[2]), "r"((a)[3]),        \
                   "r"((b)[0]), "r"((b)[1]))

// ---------------- dtype detection for edge_index ----------------
__global__ void k_detect(const int* __restrict__ ei) {
    if (threadIdx.x == 0) {
        int ornz = 0;
#pragma unroll
        for (int i = 0; i < 64; ++i) ornz |= ei[2 * i + 1];
        g_is64 = (ornz == 0) ? 1 : 0;
    }
}

__device__ __forceinline__ int2 load_edge(const void* ei, int e) {
    if (g_is64) {
        const long long* p = (const long long*)ei;
        return make_int2((int)p[e], (int)p[NE + e]);
    }
    const int* p = (const int*)ei;
    return make_int2(p[e], p[NE + e]);
}

// ---------------- CSR build ----------------
__global__ void k_zero_deg() {
    int i = blockIdx.x * 256 + threadIdx.x;
    if (i < NN) g_deg[i] = 0;
}

__global__ void __launch_bounds__(256) k_hist(const void* __restrict__ ei) {
    int e = blockIdx.x * 256 + threadIdx.x;
    if (e < NE) {
        int2 sd = load_edge(ei, e);
        atomicAdd(&g_deg[sd.y], 1);
    }
}

__global__ void __launch_bounds__(256) k_blocksum() {
    __shared__ int ws[8];
    int b = blockIdx.x;
    int i = b * 256 + threadIdx.x;
    int v = (i < NN) ? g_deg[i] : 0;
    int lane = threadIdx.x & 31, warp = threadIdx.x >> 5;
#pragma unroll
    for (int d = 16; d > 0; d >>= 1) v += __shfl_down_sync(0xffffffffu, v, d);
    if (lane == 0) ws[warp] = v;
    __syncthreads();
    if (threadIdx.x == 0) {
        int s = 0;
#pragma unroll
        for (int w = 0; w < 8; ++w) s += ws[w];
        g_bsum[b] = s;
    }
}

__global__ void __launch_bounds__(512) k_scanb() {
    __shared__ int s[512];
    int t = threadIdx.x;
    int v = (t < NB) ? g_bsum[t] : 0;
    s[t] = v;
    __syncthreads();
    for (int off = 1; off < 512; off <<= 1) {
        int u = (t >= off) ? s[t - off] : 0;
        __syncthreads();
        s[t] += u;
        __syncthreads();
    }
    if (t < NB) g_bpre[t] = s[t] - v;
}

__global__ void __launch_bounds__(256) k_offsets() {
    __shared__ int ws[8];
    int b = blockIdx.x;
    int i = b * 256 + threadIdx.x;
    int v = (i < NN) ? g_deg[i] : 0;
    int lane = threadIdx.x & 31, warp = threadIdx.x >> 5;
    int x = v;
#pragma unroll
    for (int d = 1; d < 32; d <<= 1) {
        int y = __shfl_up_sync(0xffffffffu, x, d);
        if (lane >= d) x += y;
    }
    if (lane == 31) ws[warp] = x;
    __syncthreads();
    int wpre = 0;
#pragma unroll
    for (int w = 0; w < 8; ++w) wpre += (w < warp) ? ws[w] : 0;
    int excl = g_bpre[b] + wpre + x - v;
    if (i < NN) { g_off[i] = excl; g_cur[i] = excl; }
}

__global__ void __launch_bounds__(256) k_fill(const void* __restrict__ ei) {
    int e = blockIdx.x * 256 + threadIdx.x;
    if (e < NE) {
        int2 sd = load_edge(ei, e);
        int p = atomicAdd(&g_cur[sd.y], 1);
        g_elist[p] = sd.x;
    }
}

// ---------------- fused [gather +] tf32 GEMM (128x64 tile, K=64) ----------
// 256 threads, 8 warps; warp owns 16 rows x 64 cols; 3xTF32 split.
// SMEM layout (floats), row stride 68 for conflict-free fragment loads:
//   sAhi[128*68] @0, sAlo @8704, sBhi[64*68] @17408, sBlo @21760,
//   sBias @26112(64), sWd @26176(128), sStat @26304(128), sSS @26432(128).
#define SMEM_FLOATS 26560
#define SMEM_BYTES (SMEM_FLOATS * 4)

template <bool GATHER, bool PRE_BN, bool DO_STATS, bool RELU_OUT, bool DEC>
__global__ void __launch_bounds__(256, 2) k_gemm_mma(const float* __restrict__ in,
                                                     const float* __restrict__ W,
                                                     const float* __restrict__ bias,
                                                     float* __restrict__ out,
                                                     const float* __restrict__ Wd,
                                                     const float* __restrict__ bd,
                                                     float* __restrict__ out2) {
    extern __shared__ float sm[];
    float* sAhi  = sm;
    float* sAlo  = sm + 8704;
    float* sBhi  = sm + 17408;
    float* sBlo  = sm + 21760;
    float* sBias = sm + 26112;
    float* sWd   = sm + 26176;
    float* sStat = sm + 26304;
    float* sSS   = sm + 26432;

    const int tid = threadIdx.x;
    const int wid = tid >> 5;
    const int lane = tid & 31;
    const int g = lane >> 2;         // 0..7
    const int t4 = lane & 3;         // 0..3
    const int r0 = blockIdx.x * 128;
    const int rbase = wid * 16;

    if (tid < 64) sBias[tid] = bias[tid];
    if (DEC && tid >= 64 && tid < 192) sWd[tid - 64] = Wd[tid - 64];
    if (DO_STATS && tid < 128) sStat[tid] = 0.f;
    if (PRE_BN && tid >= 128) sSS[tid - 128] = g_ss[tid - 128];
    if (PRE_BN) __syncthreads();     // sSS needed during A staging

    // ---- stage A: hi/lo tf32 split into sAhi/sAlo ----
    if (GATHER) {
        // 16 groups of 16 lanes; each group handles one row per iteration,
        // accumulating self + neighbor rows (float4 per lane).
        const float4* h4 = reinterpret_cast<const float4*>(in);
        const int grp = tid >> 4;       // 0..15
        const int l16 = tid & 15;       // 0..15
#pragma unroll 1
        for (int i = 0; i < 8; ++i) {
            int lr = i * 16 + grp;
            int node = r0 + lr;
            float4 acc = make_float4(0.f, 0.f, 0.f, 0.f);
            if (node < NN) {
                acc = h4[(size_t)node * 16 + l16];
                int off = g_off[node];
                int deg = g_deg[node];
                int j = 0;
                for (; j + 4 <= deg; j += 4) {
                    int s0 = __ldg(&g_elist[off + j + 0]);
                    int s1 = __ldg(&g_elist[off + j + 1]);
                    int s2 = __ldg(&g_elist[off + j + 2]);
                    int s3 = __ldg(&g_elist[off + j + 3]);
                    float4 v0 = h4[(size_t)s0 * 16 + l16];
                    float4 v1 = h4[(size_t)s1 * 16 + l16];
                    float4 v2 = h4[(size_t)s2 * 16 + l16];
                    float4 v3 = h4[(size_t)s3 * 16 + l16];
                    acc.x += (v0.x + v1.x) + (v2.x + v3.x);
                    acc.y += (v0.y + v1.y) + (v2.y + v3.y);
                    acc.z += (v0.z + v1.z) + (v2.z + v3.z);
                    acc.w += (v0.w + v1.w) + (v2.w + v3.w);
                }
                for (; j < deg; ++j) {
                    int s = __ldg(&g_elist[off + j]);
                    float4 v = h4[(size_t)s * 16 + l16];
                    acc.x += v.x; acc.y += v.y; acc.z += v.z; acc.w += v.w;
                }
            }
            float4 hi = make_float4(tf32_rna(acc.x), tf32_rna(acc.y),
                                    tf32_rna(acc.z), tf32_rna(acc.w));
            float4 lo = make_float4(tf32_rna(acc.x - hi.x), tf32_rna(acc.y - hi.y),
                                    tf32_rna(acc.z - hi.z), tf32_rna(acc.w - hi.w));
            int base = lr * 68 + l16 * 4;
            *reinterpret_cast<float4*>(sAhi + base) = hi;
            *reinterpret_cast<float4*>(sAlo + base) = lo;
        }
    } else {
        // row = tid>>1, k-half = tid&1 (32 k each)
        const int row = tid >> 1;
        const int kh = tid & 1;
        const bool valid = (r0 + row) < NN;
        const float4* inp = reinterpret_cast<const float4*>(in) +
                            (size_t)(r0 + row) * 16 + kh * 8;
        float* aH = sAhi + row * 68 + kh * 32;
        float* aL = sAlo + row * 68 + kh * 32;
#pragma unroll
        for (int q = 0; q < 8; ++q) {
            int k = kh * 32 + q * 4;
            float4 v = make_float4(0.f, 0.f, 0.f, 0.f);
            if (valid) v = inp[q];
            if (PRE_BN) {
                v.x = fmaxf(fmaf(v.x, sSS[k + 0], sSS[64 + k + 0]), 0.f);
                v.y = fmaxf(fmaf(v.y, sSS[k + 1], sSS[64 + k + 1]), 0.f);
                v.z = fmaxf(fmaf(v.z, sSS[k + 2], sSS[64 + k + 2]), 0.f);
                v.w = fmaxf(fmaf(v.w, sSS[k + 3], sSS[64 + k + 3]), 0.f);
            }
            float4 hi = make_float4(tf32_rna(v.x), tf32_rna(v.y), tf32_rna(v.z), tf32_rna(v.w));
            float4 lo = make_float4(tf32_rna(v.x - hi.x), tf32_rna(v.y - hi.y),
                                    tf32_rna(v.z - hi.z), tf32_rna(v.w - hi.w));
            *reinterpret_cast<float4*>(aH + q * 4) = hi;
            *reinterpret_cast<float4*>(aL + q * 4) = lo;
        }
    }

    // ---- stage B[n][k] = W[k][n], hi/lo split (n = tid&63, kh = tid>>6) ----
    {
        int n = tid & 63;
        int kh = tid >> 6;     // 0..3, 16 k each
        float* bH = sBhi + n * 68;
        float* bL = sBlo + n * 68;
#pragma unroll
        for (int qq = 0; qq < 4; ++qq) {
            int k0 = kh * 16 + qq * 4;
            float w0 = __ldg(W + (k0 + 0) * 64 + n);
            float w1 = __ldg(W + (k0 + 1) * 64 + n);
            float w2 = __ldg(W + (k0 + 2) * 64 + n);
            float w3 = __ldg(W + (k0 + 3) * 64 + n);
            float4 hi = make_float4(tf32_rna(w0), tf32_rna(w1), tf32_rna(w2), tf32_rna(w3));
            float4 lo = make_float4(tf32_rna(w0 - hi.x), tf32_rna(w1 - hi.y),
                                    tf32_rna(w2 - hi.z), tf32_rna(w3 - hi.w));
            *reinterpret_cast<float4*>(bH + k0) = hi;
            *reinterpret_cast<float4*>(bL + k0) = lo;
        }
    }
    __syncthreads();

    // ---- mainloop: 1 m-tile x 8 n-tiles, 8 k-steps, 3 splits ----
    float acc[8][4];
#pragma unroll
    for (int nt = 0; nt < 8; ++nt)
#pragma unroll
        for (int r = 0; r < 4; ++r) acc[nt][r] = 0.f;

#pragma unroll
    for (int ks = 0; ks < 8; ++ks) {
        const int k0 = ks * 8;
        uint32_t ah[4], al[4];
        {
            int rA = (rbase + g) * 68 + k0 + t4;
            int rB = rA + 8 * 68;
            ah[0] = __float_as_uint(sAhi[rA]);
            ah[1] = __float_as_uint(sAhi[rB]);
            ah[2] = __float_as_uint(sAhi[rA + 4]);
            ah[3] = __float_as_uint(sAhi[rB + 4]);
            al[0] = __float_as_uint(sAlo[rA]);
            al[1] = __float_as_uint(sAlo[rB]);
            al[2] = __float_as_uint(sAlo[rA + 4]);
            al[3] = __float_as_uint(sAlo[rB + 4]);
        }
        uint32_t bh[8][2], bl[8][2];
#pragma unroll
        for (int nt = 0; nt < 8; ++nt) {
            int nb = (nt * 8 + g) * 68 + k0 + t4;
            bh[nt][0] = __float_as_uint(sBhi[nb]);
            bh[nt][1] = __float_as_uint(sBhi[nb + 4]);
            bl[nt][0] = __float_as_uint(sBlo[nb]);
            bl[nt][1] = __float_as_uint(sBlo[nb + 4]);
        }
#pragma unroll
        for (int nt = 0; nt < 8; ++nt) {
            MMA_TF32(acc[nt], ah, bh[nt]);
            MMA_TF32(acc[nt], ah, bl[nt]);
            MMA_TF32(acc[nt], al, bh[nt]);
        }
    }

    // ---- epilogue ----
    float colsum[16], colsq[16];
    if (DO_STATS) {
#pragma unroll
        for (int i = 0; i < 16; ++i) { colsum[i] = 0.f; colsq[i] = 0.f; }
    }
    float dec_o[2][2];
    if (DEC) {
        dec_o[0][0] = dec_o[0][1] = dec_o[1][0] = dec_o[1][1] = 0.f;
    }

    const int rowA = r0 + rbase + g;
    const int rowB = rowA + 8;
    const bool vA = rowA < NN, vB = rowB < NN;
#pragma unroll
    for (int nt = 0; nt < 8; ++nt) {
        int c = nt * 8 + t4 * 2;
        float v0 = acc[nt][0] + sBias[c];
        float v1 = acc[nt][1] + sBias[c + 1];
        float v2 = acc[nt][2] + sBias[c];
        float v3 = acc[nt][3] + sBias[c + 1];
        if (RELU_OUT) {
            v0 = fmaxf(v0, 0.f); v1 = fmaxf(v1, 0.f);
            v2 = fmaxf(v2, 0.f); v3 = fmaxf(v3, 0.f);
        }
        if (vA) *reinterpret_cast<float2*>(out + (size_t)rowA * 64 + c) = make_float2(v0, v1);
        if (vB) *reinterpret_cast<float2*>(out + (size_t)rowB * 64 + c) = make_float2(v2, v3);
        if (DO_STATS) {
            if (vA) {
                colsum[nt * 2] += v0;     colsq[nt * 2] += v0 * v0;
                colsum[nt * 2 + 1] += v1; colsq[nt * 2 + 1] += v1 * v1;
            }
            if (vB) {
                colsum[nt * 2] += v2;     colsq[nt * 2] += v2 * v2;
                colsum[nt * 2 + 1] += v3; colsq[nt * 2 + 1] += v3 * v3;
            }
        }
        if (DEC) {
            dec_o[0][0] = fmaf(v0, sWd[c * 2], fmaf(v1, sWd[(c + 1) * 2], dec_o[0][0]));
            dec_o[0][1] = fmaf(v0, sWd[c * 2 + 1], fmaf(v1, sWd[(c + 1) * 2 + 1], dec_o[0][1]));
            dec_o[1][0] = fmaf(v2, sWd[c * 2], fmaf(v3, sWd[(c + 1) * 2], dec_o[1][0]));
            dec_o[1][1] = fmaf(v2, sWd[c * 2 + 1], fmaf(v3, sWd[(c + 1) * 2 + 1], dec_o[1][1]));
        }
    }

    if (DEC) {
        float bd0 = __ldg(bd + 0), bd1 = __ldg(bd + 1);
#pragma unroll
        for (int hf = 0; hf < 2; ++hf) {
            float o0 = dec_o[hf][0], o1 = dec_o[hf][1];
            o0 += __shfl_xor_sync(0xffffffffu, o0, 1);
            o0 += __shfl_xor_sync(0xffffffffu, o0, 2);
            o1 += __shfl_xor_sync(0xffffffffu, o1, 1);
            o1 += __shfl_xor_sync(0xffffffffu, o1, 2);
            int row = r0 + rbase + g + hf * 8;
            if (t4 == 0 && row < NN)
                *reinterpret_cast<float2*>(out2 + (size_t)row * 2) =
                    make_float2(o0 + bd0, o1 + bd1);
        }
    }

    if (DO_STATS) {
#pragma unroll
        for (int i = 0; i < 16; ++i) {
            colsum[i] += __shfl_down_sync(0xffffffffu, colsum[i], 4);
            colsum[i] += __shfl_down_sync(0xffffffffu, colsum[i], 8);
            colsum[i] += __shfl_down_sync(0xffffffffu, colsum[i], 16);
            colsq[i] += __shfl_down_sync(0xffffffffu, colsq[i], 4);
            colsq[i] += __shfl_down_sync(0xffffffffu, colsq[i], 8);
            colsq[i] += __shfl_down_sync(0xffffffffu, colsq[i], 16);
        }
        if (lane < 4) {
#pragma unroll
            for (int nt = 0; nt < 8; ++nt) {
                int c = nt * 8 + lane * 2;
                atomicAdd(&sStat[c], colsum[nt * 2]);
                atomicAdd(&sStat[c + 1], colsum[nt * 2 + 1]);
                atomicAdd(&sStat[64 + c], colsq[nt * 2]);
                atomicAdd(&sStat[64 + c + 1], colsq[nt * 2 + 1]);
            }
        }
        __syncthreads();
        if (tid < 128) atomicAdd(&g_stats[tid], sStat[tid]);
    }
}

// ---------------- BN finalize (also re-zeros stats for next use) ----------
__global__ void k_bn(const float* __restrict__ gamma, const float* __restrict__ beta) {
    int t = threadIdx.x;  // 64 threads
    float s = g_stats[t];
    float q = g_stats[64 + t];
    g_stats[t] = 0.f;
    g_stats[64 + t] = 0.f;
    const float inv_n = 1.0f / (float)NN;
    float mu = s * inv_n;
    float var = q * inv_n - mu * mu;
    float sc = gamma[t] * rsqrtf(var + 1e-5f);
    g_ss[t] = sc;
    g_ss[64 + t] = beta[t] - mu * sc;
}

extern "C" void kernel_launch(void* const* d_in, const int* in_sizes, int n_in,
                              void* d_out, int out_size) {
    const float* x      = (const float*)d_in[0];
    const void*  ei     = (const void*)d_in[1];
    const float* W1s    = (const float*)d_in[2];
    const float* b1s    = (const float*)d_in[3];
    const float* gammas = (const float*)d_in[4];
    const float* betas  = (const float*)d_in[5];
    const float* W2s    = (const float*)d_in[6];
    const float* b2s    = (const float*)d_in[7];
    const float* Wd     = (const float*)d_in[8];
    const float* bd     = (const float*)d_in[9];

    float* out  = (float*)d_out;          // [NN,2] logits first
    float* hout = out + 2 * NN;           // then [NN,64] embedding

    float *z, *h;
    cudaGetSymbolAddress((void**)&z, g_z);
    cudaGetSymbolAddress((void**)&h, g_h);

    // raise dynamic smem cap for the GEMM instantiations (idempotent)
    cudaFuncSetAttribute(k_gemm_mma<true, false, true, false, false>,
                         cudaFuncAttributeMaxDynamicSharedMemorySize, SMEM_BYTES);
    cudaFuncSetAttribute(k_gemm_mma<true, true, true, false, false>,
                         cudaFuncAttributeMaxDynamicSharedMemorySize, SMEM_BYTES);
    cudaFuncSetAttribute(k_gemm_mma<false, true, false, true, false>,
                         cudaFuncAttributeMaxDynamicSharedMemorySize, SMEM_BYTES);
    cudaFuncSetAttribute(k_gemm_mma<false, true, false, false, true>,
                         cudaFuncAttributeMaxDynamicSharedMemorySize, SMEM_BYTES);

    const int gemm_blocks = (NN + 127) / 128;        // 782
    const int edge_blocks = (NE + 255) / 256;        // 6250

    // CSR build (edge structure constant within a launch)
    k_detect<<<1, 32>>>((const int*)ei);
    k_zero_deg<<<NB, 256>>>();
    k_hist<<<edge_blocks, 256>>>(ei);
    k_blocksum<<<NB, 256>>>();
    k_scanb<<<1, 512>>>();
    k_offsets<<<NB, 256>>>();
    k_fill<<<edge_blocks, 256>>>(ei);

    const float* hin = x;
    for (int l = 0; l < NLAYERS; ++l) {
        // fused gather + GEMM1 (+BN stats)
        k_gemm_mma<true, false, true, false, false><<<gemm_blocks, 256, SMEM_BYTES>>>(
            hin, W1s + l * 4096, b1s + l * 64, z, nullptr, nullptr, nullptr);
        k_bn<<<1, 64>>>(gammas + l * 64, betas + l * 64);
        if (l < NLAYERS - 1) {
            k_gemm_mma<false, true, false, true, false><<<gemm_blocks, 256, SMEM_BYTES>>>(
                z, W2s + l * 4096, b2s + l * 64, h, nullptr, nullptr, nullptr);
            hin = h;
        } else {
            k_gemm_mma<false, true, false, false, true><<<gemm_blocks, 256, SMEM_BYTES>>>(
                z, W2s + l * 4096, b2s + l * 64, hout, Wd, bd, out);
            hin = hout;
        }
    }
}